// round 9
// baseline (speedup 1.0000x reference)
#include <cuda_runtime.h>

#define B_   64
#define LX_  512
#define LY_  512
#define DIM_ 64
#define BIGF 1e30f

// Diagonal-major scratch: g_Dt[b][t][i] = D[b][i][t - i], t in [0, 1023)
__device__ float g_Dt[(size_t)B_ * 1024 * 512];

typedef unsigned long long u64;

__device__ __forceinline__ u64 pack2(float lo, float hi) {
    u64 r; asm("mov.b64 %0,{%1,%2};" : "=l"(r) : "f"(lo), "f"(hi)); return r;
}
__device__ __forceinline__ u64 ffma2(u64 a, u64 b, u64 c) {
    u64 d; asm("fma.rn.f32x2 %0,%1,%2,%3;" : "=l"(d) : "l"(a), "l"(b), "l"(c)); return d;
}
__device__ __forceinline__ float2 unpack2(u64 v) {
    float2 f; asm("mov.b64 {%0,%1},%2;" : "=f"(f.x), "=f"(f.y) : "l"(v)); return f;
}
__device__ __forceinline__ float ex2_approx(float x) {
    float r; asm("ex2.approx.ftz.f32 %0,%1;" : "=f"(r) : "f"(x)); return r;
}
__device__ __forceinline__ float lg2_approx(float x) {
    float r; asm("lg2.approx.ftz.f32 %0,%1;" : "=f"(r) : "f"(x)); return r;
}

#define TP 132

// ---------------------------------------------------------------------------
// Kernel 1: batched pairwise squared-L2, 128x128 tiles, 256 threads,
// 8x8 micro-tiles, diagonal-major writeout (unchanged).
// ---------------------------------------------------------------------------
__global__ __launch_bounds__(256) void sdtw_gemm_kernel(
    const float* __restrict__ X, const float* __restrict__ Y)
{
    __shared__ float pool[2 * 32 * TP];
    float* Xs = pool;
    float* Ys = pool + 32 * TP;

    const int b  = blockIdx.z;
    const int i0 = blockIdx.y * 128;
    const int j0 = blockIdx.x * 128;
    const int tid = threadIdx.x;
    const int tx = tid & 15;
    const int ty = tid >> 4;

    const float* Xb = X + ((size_t)b * LX_ + i0) * DIM_;
    const float* Yb = Y + ((size_t)b * LY_ + j0) * DIM_;

    u64 acc2[8][4];
    u64 xn2[4], yn2[4];
    const u64 z = pack2(0.f, 0.f);
#pragma unroll
    for (int r = 0; r < 8; ++r)
#pragma unroll
        for (int p = 0; p < 4; ++p) acc2[r][p] = z;
#pragma unroll
    for (int p = 0; p < 4; ++p) { xn2[p] = z; yn2[p] = z; }

#pragma unroll 1
    for (int kh = 0; kh < 2; ++kh) {
        __syncthreads();
#pragma unroll
        for (int it = 0; it < 4; ++it) {
            int f4  = it * 256 + tid;
            int row = f4 >> 3;
            int k4  = (f4 & 7) << 2;
            float4 xv = *(const float4*)(Xb + row * DIM_ + kh * 32 + k4);
            Xs[(k4 + 0) * TP + row] = xv.x; Xs[(k4 + 1) * TP + row] = xv.y;
            Xs[(k4 + 2) * TP + row] = xv.z; Xs[(k4 + 3) * TP + row] = xv.w;
            float4 yv = *(const float4*)(Yb + row * DIM_ + kh * 32 + k4);
            Ys[(k4 + 0) * TP + row] = yv.x; Ys[(k4 + 1) * TP + row] = yv.y;
            Ys[(k4 + 2) * TP + row] = yv.z; Ys[(k4 + 3) * TP + row] = yv.w;
        }
        __syncthreads();

#pragma unroll 8
        for (int k = 0; k < 32; ++k) {
            float4 xa = *(const float4*)&Xs[k * TP + ty * 8];
            float4 xb = *(const float4*)&Xs[k * TP + ty * 8 + 4];
            float4 ya = *(const float4*)&Ys[k * TP + tx * 8];
            float4 yb = *(const float4*)&Ys[k * TP + tx * 8 + 4];
            u64 yp[4] = { pack2(ya.x, ya.y), pack2(ya.z, ya.w),
                          pack2(yb.x, yb.y), pack2(yb.z, yb.w) };
            float xs[8] = {xa.x, xa.y, xa.z, xa.w, xb.x, xb.y, xb.z, xb.w};
#pragma unroll
            for (int r = 0; r < 8; ++r) {
                u64 xp = pack2(xs[r], xs[r]);
#pragma unroll
                for (int p = 0; p < 4; ++p)
                    acc2[r][p] = ffma2(xp, yp[p], acc2[r][p]);
            }
            u64 xq[4] = { pack2(xa.x, xa.y), pack2(xa.z, xa.w),
                          pack2(xb.x, xb.y), pack2(xb.z, xb.w) };
#pragma unroll
            for (int p = 0; p < 4; ++p) {
                xn2[p] = ffma2(xq[p], xq[p], xn2[p]);
                yn2[p] = ffma2(yp[p], yp[p], yn2[p]);
            }
        }
    }

    float xn[8], yn[8], dres[8][8];
#pragma unroll
    for (int p = 0; p < 4; ++p) {
        float2 xv = unpack2(xn2[p]); xn[2*p] = xv.x; xn[2*p+1] = xv.y;
        float2 yv = unpack2(yn2[p]); yn[2*p] = yv.x; yn[2*p+1] = yv.y;
    }
#pragma unroll
    for (int r = 0; r < 8; ++r)
#pragma unroll
        for (int p = 0; p < 4; ++p) {
            float2 a = unpack2(acc2[r][p]);
            dres[r][2*p]   = fmaf(-2.0f, a.x, xn[r] + yn[2*p]);
            dres[r][2*p+1] = fmaf(-2.0f, a.y, xn[r] + yn[2*p+1]);
        }

    const int CP = 66;
    float* stage = pool;
    const int g  = tid >> 6;
    const int li = tid & 63;
#pragma unroll 1
    for (int q = 0; q < 4; ++q) {
        int qi = q >> 1, qj = q & 1;
        __syncthreads();
        if ((ty >> 3) == qi && (tx >> 3) == qj) {
            int r0 = (ty & 7) * 8, c0 = (tx & 7) * 8;
#pragma unroll
            for (int r = 0; r < 8; ++r)
#pragma unroll
                for (int c = 0; c < 8; ++c)
                    stage[(r0 + r) * CP + (c0 + c)] = dres[r][c];
        }
        __syncthreads();
        int i0q = i0 + qi * 64, j0q = j0 + qj * 64;
        float* Dtb = g_Dt + (size_t)b * (1024 * 512)
                   + (size_t)(i0q + j0q) * 512 + i0q;
        for (int tl = g; tl < 127; tl += 4) {
            int ilo = tl - 63; if (ilo < 0) ilo = 0;
            int ihi = tl;      if (ihi > 63) ihi = 63;
            if (li >= ilo && li <= ihi)
                Dtb[(size_t)tl * 512 + li] = stage[li * (CP - 1) + tl];
        }
    }
}

// ---------------------------------------------------------------------------
// Kernel 2: warp-pipelined soft-DTW wavefront.
// Chunk-burst double-buffered D loads (no LDG or address math inside the
// step loop); 3-exp softmin (shortest dependency depth); one shfl/step;
// pipelined warp-uniform boundary LDS; predicated lane-31 STS publish.
// Answer read from bnd[15][512] (written once at s=542).
// ---------------------------------------------------------------------------
__global__ __launch_bounds__(512) void sdtw_dp_kernel(float* __restrict__ out)
{
    __shared__ float bnd[16][520];   // bnd[w][c+1] = R[32w+31][c]; [w][0]=BIG

    const int tid = threadIdx.x;
    const int w = tid >> 5;
    const int l = tid & 31;
    const int b = blockIdx.x;

    if (l == 0) bnd[w][0] = BIGF;

    // DW[s*512] = Dt[b][32w+s][32w+l]
    const float* __restrict__ DW =
        g_Dt + (size_t)b * (1024 * 512) + (size_t)(32 * w) * 512 + 32 * w + l;

    float a1 = BIGF;                             // R[i][j-1]
    float prev_up = (tid == 0) ? 0.0f : BIGF;    // becomes diag dep next step

    float dA[16], dB[16];                        // chunk double buffer
#pragma unroll
    for (int u = 0; u < 16; ++u)                 // chunk 0 burst (hidden by LAG)
        dA[u] = __ldg(DW + (size_t)u * 512);

    __syncthreads();

    const float L2E = 1.44269504f;
    const float LN2 = 0.69314718f;
    const int NCH = 34;              // ceil(543/16); last chunk pads to s=543
    const int LAG = 3;
    const int P = 15 * LAG + NCH;    // 79 phases
    const float* bprev = bnd[(w > 0) ? (w - 1) : 0];
    const bool lane0   = (l == 0);
    const bool w0lane0 = (w == 0) && lane0;
    const bool lane31  = (l == 31);

#pragma unroll 1
    for (int p = 0; p < P; ++p) {
        int q = p - LAG * w;
        if (q >= 0 && q < NCH) {                 // warp-uniform
            int s0 = q * 16;

            // burst-issue next chunk's 16 loads (complete during this chunk)
#pragma unroll
            for (int u = 0; u < 16; ++u) {
                int sp = s0 + 16 + u; if (sp > 542) sp = 542;
                dB[u] = __ldg(DW + (size_t)sp * 512);
            }

            // boundary for the chunk's first step (warp-uniform address)
            int jc0 = (s0 > 511) ? 511 : s0;
            float bcur = bprev[jc0 + 1];

#pragma unroll
            for (int u = 0; u < 16; ++u) {
                int s = s0 + u;

                // prefetch next step's boundary (within-chunk only)
                int sn = (u < 15) ? (s + 1) : s;
                int jn = (sn > 511) ? 511 : sn;
                float bnext = bprev[jn + 1];

                float up_sh = __shfl_up_sync(0xFFFFFFFFu, a1, 1);
                float up = lane0 ? (w0lane0 ? BIGF : bcur) : up_sh;
                float dg = prev_up;              // == up from previous step
                int j = s - l;
                float lf = (j >= 1) ? a1 : BIGF;

                // 3-exp softmin (shortest chain; MUFU tput has headroom)
                float m  = fminf(fminf(up, dg), lf);
                float mc = m * L2E;
                float eu = ex2_approx(fmaf(-L2E, up, mc));
                float ed = ex2_approx(fmaf(-L2E, dg, mc));
                float el = ex2_approx(fmaf(-L2E, lf, mc));
                float s3 = (eu + ed) + el;
                float smin = fmaf(-LN2, lg2_approx(s3), m);

                float rc = ((unsigned)j <= 511u) ? (dA[u] + smin) : BIGF;
                prev_up = up;
                a1 = rc;
                bcur = bnext;

                // single predicated STS publish of bottom row
                if (lane31 && (unsigned)j <= 511u) bnd[w][j + 1] = rc;
            }

            // recycle buffers (LDGs above have long completed)
#pragma unroll
            for (int u = 0; u < 16; ++u) dA[u] = dB[u];
        }
        __syncthreads();
    }

    // R[511][511] published by warp 15, lane 31 at s=542 (j=511).
    if (tid == 0) out[b] = bnd[15][512];
}

// ---------------------------------------------------------------------------
extern "C" void kernel_launch(void* const* d_in, const int* in_sizes, int n_in,
                              void* d_out, int out_size)
{
    (void)in_sizes; (void)n_in; (void)out_size;
    const float* X = (const float*)d_in[0];
    const float* Y = (const float*)d_in[1];
    float* out = (float*)d_out;

    dim3 gg(LY_ / 128, LX_ / 128, B_);
    sdtw_gemm_kernel<<<gg, 256>>>(X, Y);
    sdtw_dp_kernel<<<B_, 512>>>(out);
}

// round 10
// speedup vs baseline: 1.2708x; 1.2708x over previous
#include <cuda_runtime.h>

#define B_   64
#define LX_  512
#define LY_  512
#define DIM_ 64
#define BIGF 1e30f

// Pair-major scratch: g_Dp[PAD2 + b*(256*512) + m*512 + i] = {D[i][2m], D[i][2m+1]}
// Padding on both sides so the DP prefetch ring may harmlessly read out of range.
#define PAD2 32768
__device__ float2 g_Dp[2 * PAD2 + (size_t)B_ * 256 * 512];

typedef unsigned long long u64;

__device__ __forceinline__ u64 pack2(float lo, float hi) {
    u64 r; asm("mov.b64 %0,{%1,%2};" : "=l"(r) : "f"(lo), "f"(hi)); return r;
}
__device__ __forceinline__ u64 ffma2(u64 a, u64 b, u64 c) {
    u64 d; asm("fma.rn.f32x2 %0,%1,%2,%3;" : "=l"(d) : "l"(a), "l"(b), "l"(c)); return d;
}
__device__ __forceinline__ float2 unpack2(u64 v) {
    float2 f; asm("mov.b64 {%0,%1},%2;" : "=f"(f.x), "=f"(f.y) : "l"(v)); return f;
}
__device__ __forceinline__ float ex2_approx(float x) {
    float r; asm("ex2.approx.ftz.f32 %0,%1;" : "=f"(r) : "f"(x)); return r;
}
__device__ __forceinline__ float lg2_approx(float x) {
    float r; asm("lg2.approx.ftz.f32 %0,%1;" : "=f"(r) : "f"(x)); return r;
}

#define TP 132

// ---------------------------------------------------------------------------
// Kernel 1: batched pairwise squared-L2, 128x128 tiles, 256 threads,
// 8x8 micro-tiles; writeout now pair-major (simple transpose, conflict-free).
// ---------------------------------------------------------------------------
__global__ __launch_bounds__(256) void sdtw_gemm_kernel(
    const float* __restrict__ X, const float* __restrict__ Y)
{
    __shared__ float pool[2 * 32 * TP];
    float* Xs = pool;
    float* Ys = pool + 32 * TP;

    const int b  = blockIdx.z;
    const int i0 = blockIdx.y * 128;
    const int j0 = blockIdx.x * 128;
    const int tid = threadIdx.x;
    const int tx = tid & 15;
    const int ty = tid >> 4;

    const float* Xb = X + ((size_t)b * LX_ + i0) * DIM_;
    const float* Yb = Y + ((size_t)b * LY_ + j0) * DIM_;

    u64 acc2[8][4];
    u64 xn2[4], yn2[4];
    const u64 z = pack2(0.f, 0.f);
#pragma unroll
    for (int r = 0; r < 8; ++r)
#pragma unroll
        for (int p = 0; p < 4; ++p) acc2[r][p] = z;
#pragma unroll
    for (int p = 0; p < 4; ++p) { xn2[p] = z; yn2[p] = z; }

#pragma unroll 1
    for (int kh = 0; kh < 2; ++kh) {
        __syncthreads();
#pragma unroll
        for (int it = 0; it < 4; ++it) {
            int f4  = it * 256 + tid;
            int row = f4 >> 3;
            int k4  = (f4 & 7) << 2;
            float4 xv = *(const float4*)(Xb + row * DIM_ + kh * 32 + k4);
            Xs[(k4 + 0) * TP + row] = xv.x; Xs[(k4 + 1) * TP + row] = xv.y;
            Xs[(k4 + 2) * TP + row] = xv.z; Xs[(k4 + 3) * TP + row] = xv.w;
            float4 yv = *(const float4*)(Yb + row * DIM_ + kh * 32 + k4);
            Ys[(k4 + 0) * TP + row] = yv.x; Ys[(k4 + 1) * TP + row] = yv.y;
            Ys[(k4 + 2) * TP + row] = yv.z; Ys[(k4 + 3) * TP + row] = yv.w;
        }
        __syncthreads();

#pragma unroll 8
        for (int k = 0; k < 32; ++k) {
            float4 xa = *(const float4*)&Xs[k * TP + ty * 8];
            float4 xb = *(const float4*)&Xs[k * TP + ty * 8 + 4];
            float4 ya = *(const float4*)&Ys[k * TP + tx * 8];
            float4 yb = *(const float4*)&Ys[k * TP + tx * 8 + 4];
            u64 yp[4] = { pack2(ya.x, ya.y), pack2(ya.z, ya.w),
                          pack2(yb.x, yb.y), pack2(yb.z, yb.w) };
            float xs[8] = {xa.x, xa.y, xa.z, xa.w, xb.x, xb.y, xb.z, xb.w};
#pragma unroll
            for (int r = 0; r < 8; ++r) {
                u64 xp = pack2(xs[r], xs[r]);
#pragma unroll
                for (int p = 0; p < 4; ++p)
                    acc2[r][p] = ffma2(xp, yp[p], acc2[r][p]);
            }
            u64 xq[4] = { pack2(xa.x, xa.y), pack2(xa.z, xa.w),
                          pack2(xb.x, xb.y), pack2(xb.z, xb.w) };
#pragma unroll
            for (int p = 0; p < 4; ++p) {
                xn2[p] = ffma2(xq[p], xq[p], xn2[p]);
                yn2[p] = ffma2(yp[p], yp[p], yn2[p]);
            }
        }
    }

    float xn[8], yn[8], dres[8][8];
#pragma unroll
    for (int p = 0; p < 4; ++p) {
        float2 xv = unpack2(xn2[p]); xn[2*p] = xv.x; xn[2*p+1] = xv.y;
        float2 yv = unpack2(yn2[p]); yn[2*p] = yv.x; yn[2*p+1] = yv.y;
    }
#pragma unroll
    for (int r = 0; r < 8; ++r)
#pragma unroll
        for (int p = 0; p < 4; ++p) {
            float2 a = unpack2(acc2[r][p]);
            dres[r][2*p]   = fmaf(-2.0f, a.x, xn[r] + yn[2*p]);
            dres[r][2*p+1] = fmaf(-2.0f, a.y, xn[r] + yn[2*p+1]);
        }

    // Pair-major writeout per 64x64 quadrant via smem stage.
    const int CP = 66;
    float* stage = pool;
    const int g  = tid >> 6;
    const int li = tid & 63;
#pragma unroll 1
    for (int q = 0; q < 4; ++q) {
        int qi = q >> 1, qj = q & 1;
        __syncthreads();
        if ((ty >> 3) == qi && (tx >> 3) == qj) {
            int r0 = (ty & 7) * 8, c0 = (tx & 7) * 8;
#pragma unroll
            for (int r = 0; r < 8; ++r)
#pragma unroll
                for (int c = 0; c < 8; ++c)
                    stage[(r0 + r) * CP + (c0 + c)] = dres[r][c];
        }
        __syncthreads();
        int i0q = i0 + qi * 64, j0q = j0 + qj * 64;
        float2* Dpb = g_Dp + PAD2 + (size_t)b * (256 * 512)
                    + (size_t)(j0q >> 1) * 512 + i0q;
#pragma unroll
        for (int ml = g; ml < 32; ml += 4) {
            float2 v;
            v.x = stage[li * CP + 2 * ml];
            v.y = stage[li * CP + 2 * ml + 1];
            Dpb[(size_t)ml * 512 + li] = v;
        }
    }
}

// ---------------------------------------------------------------------------
// Kernel 2: warp-pipelined soft-DTW wavefront, TWO columns per step.
// Lane l of warp w owns row i=32w+l; at local step s it computes cells
// (i, 2(s-l)) and (i, 2(s-l)+1). Up-pair via 2 shfls of neighbor's prev
// (rc0, rc1); dg0 = previous step's up1 (register); dg1 = up0; lf0 = own
// prev rc1; lf1 = rc0. One coalesced LDG.64 of the D pair per step.
// Chunks C=16 steps (32 columns), producer lag 3 -> 63 phases.
// ---------------------------------------------------------------------------
__global__ __launch_bounds__(512) void sdtw_dp_kernel(float* __restrict__ out)
{
    __shared__ float2 bndp[16][256];  // bndp[w][m] = {R[32w+31][2m], R[32w+31][2m+1]}

    const int tid = threadIdx.x;
    const int w = tid >> 5;
    const int l = tid & 31;
    const int b = blockIdx.x;

    // Per-lane base: element for local step s lives at DW[s * 512].
    const float2* __restrict__ DW =
        g_Dp + PAD2 + (size_t)b * (256 * 512) + (32 * w + l) - (ptrdiff_t)l * 512;

    float c0 = BIGF;                              // own rc0 from prev step
    float a1 = BIGF;                              // own rc1 from prev step
    float prev_u1 = (tid == 0) ? 0.0f : BIGF;     // diag seed / prev step's up1

    float2 dring[16];                             // depth-16 prefetch ring
#pragma unroll
    for (int u = 0; u < 16; ++u) dring[u] = DW[(size_t)u * 512];

    __syncthreads();

    const float L2E = 1.44269504f;
    const float LN2 = 0.69314718f;
    const int NCH = 18;               // ceil(287/16); covers local steps 0..287
    const int LAG = 3;
    const int P = 15 * LAG + NCH;     // 63 phases
    const float2* bprev = bndp[(w > 0) ? (w - 1) : 0];
    const bool lane0  = (l == 0);
    const bool w0     = (w == 0);
    const bool lane31 = (l == 31);

#pragma unroll 1
    for (int p = 0; p < P; ++p) {
        int q = p - LAG * w;
        if (q >= 0 && q < NCH) {                  // warp-uniform
            int s0 = q * 16;
            int mb0 = (s0 > 255) ? 255 : s0;
            float2 bcur = bprev[mb0];             // {R[32w-1][2s], R[32w-1][2s+1]}
#pragma unroll
            for (int u = 0; u < 16; ++u) {
                int s = s0 + u;
                float2 d = dring[u];
                dring[u] = DW[(size_t)(s + 16) * 512];   // ring refill (padded OK)

                int mbn = (s + 1 > 255) ? 255 : (s + 1);
                float2 bnext = bprev[mbn];        // warp-uniform broadcast

                float up0s = __shfl_up_sync(0xFFFFFFFFu, c0, 1);
                float up1s = __shfl_up_sync(0xFFFFFFFFu, a1, 1);
                float up0 = lane0 ? (w0 ? BIGF : bcur.x) : up0s;
                float up1 = lane0 ? (w0 ? BIGF : bcur.y) : up1s;

                int sl = s - l;
                bool valid = ((unsigned)sl <= 255u);   // both cells share validity

                // cell 0: j0 = 2(s-l)
                float dg0 = prev_u1;
                float lf0 = a1;
                float m0  = fminf(fminf(up0, dg0), lf0);
                float mc0 = m0 * L2E;
                float e0a = ex2_approx(fmaf(-L2E, up0, mc0));
                float e0b = ex2_approx(fmaf(-L2E, dg0, mc0));
                float e0c = ex2_approx(fmaf(-L2E, lf0, mc0));
                float s30 = (e0a + e0b) + e0c;
                float rc0v = fmaf(-LN2, lg2_approx(s30), m0 + d.x);
                float rc0 = valid ? rc0v : BIGF;

                // cell 1: j1 = j0 + 1
                float dg1 = up0;
                float lf1 = rc0;
                float m1  = fminf(fminf(up1, dg1), lf1);
                float mc1 = m1 * L2E;
                float e1a = ex2_approx(fmaf(-L2E, up1, mc1));
                float e1b = ex2_approx(fmaf(-L2E, dg1, mc1));
                float e1c = ex2_approx(fmaf(-L2E, lf1, mc1));
                float s31 = (e1a + e1b) + e1c;
                float rc1v = fmaf(-LN2, lg2_approx(s31), m1 + d.y);
                float rc1 = valid ? rc1v : BIGF;

                prev_u1 = up1;
                c0 = rc0;
                a1 = rc1;
                bcur = bnext;

                // single predicated STS.64 publish of bottom row pair
                if (lane31 && valid) bndp[w][sl] = make_float2(rc0, rc1);
            }
        }
        __syncthreads();
    }

    // R[511][511] = second element of warp 15's pair at m=255 (s=286).
    if (tid == 0) out[b] = bndp[15][255].y;
}

// ---------------------------------------------------------------------------
extern "C" void kernel_launch(void* const* d_in, const int* in_sizes, int n_in,
                              void* d_out, int out_size)
{
    (void)in_sizes; (void)n_in; (void)out_size;
    const float* X = (const float*)d_in[0];
    const float* Y = (const float*)d_in[1];
    float* out = (float*)d_out;

    dim3 gg(LY_ / 128, LX_ / 128, B_);
    sdtw_gemm_kernel<<<gg, 256>>>(X, Y);
    sdtw_dp_kernel<<<B_, 512>>>(out);
}